// round 14
// baseline (speedup 1.0000x reference)
#include <cuda_runtime.h>
#include <cuda_fp16.h>
#include <math.h>

// Problem dims (fixed by the dataset)
#define NBATCH 128
#define NI     2048
#define DI     16
#define NO     32
#define DO     16
#define JD     (NO * DO)          // 512

#define II     16                 // i's per CTA (both big kernels)
#define NIB    (NI / II)          // 128 i-blocks
#define NELEM  (NBATCH * JD)      // 65536

// Deterministic buffers (no atomics anywhere). X_hat is NEVER materialized.
__device__ float  g_S0part[(size_t)NIB * NBATCH * JD];       // 33.5 MB
__device__ float  g_S1part[(size_t)NIB * NBATCH * JD];       // 33.5 MB
__device__ float  g_red0[4 * NELEM];                         // 1 MB
__device__ float  g_red1[4 * NELEM];                         // 1 MB
__device__ float  g_V0[NBATCH * JD];

// ---------------------------------------------------------------------------
// mma.sync m16n8k16 f16 -> f32
// ---------------------------------------------------------------------------
__device__ __forceinline__ void mma16816(float& d0, float& d1, float& d2, float& d3,
                                         unsigned a0, unsigned a1, unsigned a2, unsigned a3,
                                         unsigned b0, unsigned b1)
{
    asm volatile(
        "mma.sync.aligned.m16n8k16.row.col.f32.f16.f16.f32 "
        "{%0,%1,%2,%3}, {%4,%5,%6,%7}, {%8,%9}, {%10,%11,%12,%13};"
        : "=f"(d0), "=f"(d1), "=f"(d2), "=f"(d3)
        : "r"(a0), "r"(a1), "r"(a2), "r"(a3), "r"(b0), "r"(b1),
          "f"(0.0f), "f"(0.0f), "f"(0.0f), "f"(0.0f));
}

__device__ __forceinline__ unsigned pkh2(float x, float y) {
    __half2 h = __floats2half2_rn(x, y);
    return *reinterpret_cast<unsigned*>(&h);
}

// ---------------------------------------------------------------------------
// K1-lite: S0 partials via tensor cores (NO X_hat store).
// grid (4 nq, NIB), block 256 (8 warps), 2 CTAs/SM.  R12 K1 minus Osm.
// ---------------------------------------------------------------------------
__global__ __launch_bounds__(256, 2)
void caps_s0_mma(const float* __restrict__ X, const float* __restrict__ W)
{
    __shared__ __align__(16) __half Wsm[128 * 16];        // 4 KB  [nlocal][k]
    __shared__ __align__(16) __half Xsm[128 * 16];        // 4 KB  [b][k]

    const int nq    = blockIdx.x;
    const int iblk  = blockIdx.y;
    const int t     = threadIdx.x;
    const int w     = t >> 5;
    const int l     = t & 31;
    const int g     = l >> 2;
    const int tq    = l & 3;
    const int nbase = nq * 128;

    unsigned* Wu = reinterpret_cast<unsigned*>(Wsm);
    unsigned* Xu = reinterpret_cast<unsigned*>(Xsm);

    float s0[16][4];
#pragma unroll
    for (int q = 0; q < 16; ++q) { s0[q][0]=0.f; s0[q][1]=0.f; s0[q][2]=0.f; s0[q][3]=0.f; }

    for (int ii = 0; ii < II; ++ii) {
        const int i = iblk * II + ii;
        __syncthreads();
#pragma unroll
        for (int r = 0; r < 2; ++r) {
            int e  = t + r * 256;
            int nl = e >> 2, k4 = e & 3;
            float4 v = *reinterpret_cast<const float4*>(
                W + ((size_t)i * JD + nbase + nl) * DI + k4 * 4);
            uint2 h; h.x = pkh2(v.x, v.y); h.y = pkh2(v.z, v.w);
            *reinterpret_cast<uint2*>(Wu + nl * 8 + k4 * 2) = h;
        }
#pragma unroll
        for (int r = 0; r < 2; ++r) {
            int e = t + r * 256;
            int b = e >> 2, k4 = e & 3;
            float4 v = *reinterpret_cast<const float4*>(
                X + ((size_t)b * NI + i) * DI + k4 * 4);
            uint2 h; h.x = pkh2(v.x, v.y); h.y = pkh2(v.z, v.w);
            *reinterpret_cast<uint2*>(Xu + b * 8 + k4 * 2) = h;
        }
        __syncthreads();

        unsigned a[8][4];
#pragma unroll
        for (int mt = 0; mt < 8; ++mt) {
            int base = (mt * 16 + g) * 8 + tq;
            a[mt][0] = Xu[base];
            a[mt][1] = Xu[base + 64];
            a[mt][2] = Xu[base + 4];
            a[mt][3] = Xu[base + 68];
        }
        unsigned bf[2][2];
#pragma unroll
        for (int nt = 0; nt < 2; ++nt) {
            int base = (w * 16 + nt * 8 + g) * 8 + tq;
            bf[nt][0] = Wu[base];
            bf[nt][1] = Wu[base + 4];
        }

#pragma unroll
        for (int nt = 0; nt < 2; ++nt) {
#pragma unroll
            for (int mt = 0; mt < 8; ++mt) {
                float d0, d1, d2, d3;
                mma16816(d0, d1, d2, d3,
                         a[mt][0], a[mt][1], a[mt][2], a[mt][3],
                         bf[nt][0], bf[nt][1]);
                float* s = s0[nt * 8 + mt];
                s[0] += d0; s[1] += d1; s[2] += d2; s[3] += d3;
            }
        }
    }

    float* outp = g_S0part + (size_t)iblk * NELEM;
#pragma unroll
    for (int nt = 0; nt < 2; ++nt) {
        const int n = nbase + w * 16 + nt * 8 + tq * 2;
#pragma unroll
        for (int mt = 0; mt < 8; ++mt) {
            const float* s = s0[nt * 8 + mt];
            const int bq = mt * 16 + g;
            *reinterpret_cast<float2*>(&outp[(size_t)bq * JD + n])
                = make_float2(s[0], s[1]);
            *reinterpret_cast<float2*>(&outp[(size_t)(bq + 8) * JD + n])
                = make_float2(s[2], s[3]);
        }
    }
}

// ---------------------------------------------------------------------------
// K2a: stage-A reduce of S0 partials. 262144 threads, (elem, c-quarter).
// ---------------------------------------------------------------------------
__global__ void caps_red_s0()
{
    int t    = blockIdx.x * blockDim.x + threadIdx.x;
    int elem = t & (NELEM - 1);
    int cq   = t >> 16;
    float s = 0.f;
#pragma unroll 4
    for (int c = cq * (NIB/4); c < (cq + 1) * (NIB/4); ++c)
        s += g_S0part[(size_t)c * NELEM + elem];
    g_red0[t] = s;
}

// ---------------------------------------------------------------------------
// K2b: sum 4 stage-A partials + squash -> g_V0.
// ---------------------------------------------------------------------------
__global__ void caps_squash_v0()
{
    int t = blockIdx.x * blockDim.x + threadIdx.x;
    float s = g_red0[t] + g_red0[NELEM + t] + g_red0[2*NELEM + t] + g_red0[3*NELEM + t];
    s *= (1.0f / NO);
    float n2 = s * s;
#pragma unroll
    for (int off = 1; off < 16; off <<= 1)
        n2 += __shfl_xor_sync(0xffffffffu, n2, off);
    float f = sqrtf(n2) / (1.0f + n2);
    g_V0[t] = s * f;
}

// ---------------------------------------------------------------------------
// K3-fused: recompute X_hat via mma (twice per i) and route, no global X_hat.
// grid (8 bq, NIB), block 256 (8 warps), 2 CTAs/SM.
// CTA: 16 b x 512 n x II i's. Warp w owns n in [64w, 64w+64) => j in [4w,4w+4).
// Per i: stage W/X -> mma pass1 -> frag-distributed b1 dot (quad shfl) ->
// smem exchange -> warp softmax -> mma pass2 -> c-weighted S1 accumulation.
// ---------------------------------------------------------------------------
__global__ __launch_bounds__(256, 2)
void caps_route_fused(const float* __restrict__ X, const float* __restrict__ W)
{
    __shared__ __align__(16) __half Wsm[512 * 16];   // 16 KB [n][k]
    __shared__ __align__(16) __half Xsm[16 * 16];    // 512 B [b][k]
    __shared__ float Bsm[16 * 33];                   // b1 logits [blocal][j]
    __shared__ float Csm[16 * 33];                   // softmax  [blocal][j]

    const int bq   = blockIdx.x;       // 0..7
    const int iblk = blockIdx.y;       // 0..127
    const int t    = threadIdx.x;
    const int w    = t >> 5;
    const int l    = t & 31;
    const int g    = l >> 2;
    const int tq   = l & 3;
    const int Bb   = bq * 16;          // global b base

    unsigned* Wu = reinterpret_cast<unsigned*>(Wsm);
    unsigned* Xu = reinterpret_cast<unsigned*>(Xsm);

    // v0 for this lane's fixed (rows {Bb+g, Bb+g+8}, cols per nt) -- half2 regs
    unsigned vreg[8][2];
#pragma unroll
    for (int nt = 0; nt < 8; ++nt)
#pragma unroll
        for (int rr = 0; rr < 2; ++rr) {
            float2 vv = *reinterpret_cast<const float2*>(
                &g_V0[(size_t)(Bb + g + 8*rr) * JD + w * 64 + nt * 8 + tq * 2]);
            vreg[nt][rr] = pkh2(vv.x, vv.y);
        }

    float s1[8][4];
#pragma unroll
    for (int q = 0; q < 8; ++q) { s1[q][0]=0.f; s1[q][1]=0.f; s1[q][2]=0.f; s1[q][3]=0.f; }

    for (int ii = 0; ii < II; ++ii) {
        const int i = iblk * II + ii;
        __syncthreads();   // prev-iter Csm reads done; Wsm/Xsm free

        // stage W: all 512 n x 16 k, fp32 -> fp16 (2048 float4, 8/thread)
#pragma unroll
        for (int r = 0; r < 8; ++r) {
            int e = t + r * 256;
            int n = e >> 2, q = e & 3;
            float4 v = *reinterpret_cast<const float4*>(
                W + ((size_t)i * JD + n) * DI + q * 4);
            uint2 h; h.x = pkh2(v.x, v.y); h.y = pkh2(v.z, v.w);
            *reinterpret_cast<uint2*>(Wu + n * 8 + q * 2) = h;
        }
        // stage X: 16 b x 16 k (128 float4, threads < 128)
        if (t < 128) {
            int b = t >> 2, q = t & 3;
            float4 v = *reinterpret_cast<const float4*>(
                X + ((size_t)(Bb + b) * NI + i) * DI + q * 4);
            uint2 h; h.x = pkh2(v.x, v.y); h.y = pkh2(v.z, v.w);
            *reinterpret_cast<uint2*>(Xu + b * 8 + q * 2) = h;
        }
        __syncthreads();

        // A frags (one m-tile: rows 0-15 = the CTA's 16 b)
        unsigned a0 = Xu[g * 8 + tq];
        unsigned a1 = Xu[(g + 8) * 8 + tq];
        unsigned a2 = Xu[g * 8 + tq + 4];
        unsigned a3 = Xu[(g + 8) * 8 + tq + 4];
        // B frags: this warp's 8 n-tiles
        unsigned bf[8][2];
#pragma unroll
        for (int nt = 0; nt < 8; ++nt) {
            int base = (w * 64 + nt * 8 + g) * 8 + tq;
            bf[nt][0] = Wu[base];
            bf[nt][1] = Wu[base + 4];
        }

        // --- pass 1: mma + b1 dot partials (4 cols per lane per j) ---
        float pa[2][4];
#pragma unroll
        for (int rr = 0; rr < 2; ++rr)
#pragma unroll
            for (int jj = 0; jj < 4; ++jj) pa[rr][jj] = 0.f;

#pragma unroll
        for (int nt = 0; nt < 8; ++nt) {
            float d0, d1, d2, d3;
            mma16816(d0, d1, d2, d3, a0, a1, a2, a3, bf[nt][0], bf[nt][1]);
            float2 va = __half22float2(*reinterpret_cast<const __half2*>(&vreg[nt][0]));
            float2 vb = __half22float2(*reinterpret_cast<const __half2*>(&vreg[nt][1]));
            const int jj = nt >> 1;
            pa[0][jj] = fmaf(d0, va.x, fmaf(d1, va.y, pa[0][jj]));
            pa[1][jj] = fmaf(d2, vb.x, fmaf(d3, vb.y, pa[1][jj]));
        }
        // quad reduce over tq (lane bits 0-1) -> full b1 at tq==0
#pragma unroll
        for (int rr = 0; rr < 2; ++rr)
#pragma unroll
            for (int jj = 0; jj < 4; ++jj) {
                float x = pa[rr][jj];
                x += __shfl_xor_sync(0xffffffffu, x, 1);
                x += __shfl_xor_sync(0xffffffffu, x, 2);
                pa[rr][jj] = x;
            }
        if (tq == 0) {
#pragma unroll
            for (int rr = 0; rr < 2; ++rr)
#pragma unroll
                for (int jj = 0; jj < 4; ++jj)
                    Bsm[(g + 8*rr) * 33 + 4*w + jj] = pa[rr][jj];
        }
        __syncthreads();

        // --- softmax over j (32 lanes = 32 j), warp w handles rows 2w, 2w+1 ---
#pragma unroll
        for (int rr = 0; rr < 2; ++rr) {
            int br = 2*w + rr;
            float e = __expf(Bsm[br * 33 + l]);   // logits bounded, no max pass
            float ss = e;
#pragma unroll
            for (int off = 16; off; off >>= 1)
                ss += __shfl_xor_sync(0xffffffffu, ss, off);
            Csm[br * 33 + l] = e / ss;
        }
        __syncthreads();

        // --- pass 2: re-run mma, accumulate c * xhat into s1 frags ---
        float cg[2][4];
#pragma unroll
        for (int rr = 0; rr < 2; ++rr)
#pragma unroll
            for (int jj = 0; jj < 4; ++jj)
                cg[rr][jj] = Csm[(g + 8*rr) * 33 + 4*w + jj];

#pragma unroll
        for (int nt = 0; nt < 8; ++nt) {
            float d0, d1, d2, d3;
            mma16816(d0, d1, d2, d3, a0, a1, a2, a3, bf[nt][0], bf[nt][1]);
            const int jj = nt >> 1;
            s1[nt][0] = fmaf(cg[0][jj], d0, s1[nt][0]);
            s1[nt][1] = fmaf(cg[0][jj], d1, s1[nt][1]);
            s1[nt][2] = fmaf(cg[1][jj], d2, s1[nt][2]);
            s1[nt][3] = fmaf(cg[1][jj], d3, s1[nt][3]);
        }
    }

    // write S1 partials: [iblk][b][n]
    float* o = g_S1part + (size_t)iblk * NELEM;
#pragma unroll
    for (int nt = 0; nt < 8; ++nt) {
        const int n = w * 64 + nt * 8 + tq * 2;
        *reinterpret_cast<float2*>(&o[(size_t)(Bb + g) * JD + n])
            = make_float2(s1[nt][0], s1[nt][1]);
        *reinterpret_cast<float2*>(&o[(size_t)(Bb + g + 8) * JD + n])
            = make_float2(s1[nt][2], s1[nt][3]);
    }
}

// ---------------------------------------------------------------------------
// K4a: stage-A reduce of S1 partials (now NIB chunks). 262144 threads.
// ---------------------------------------------------------------------------
__global__ void caps_red_s1()
{
    int t    = blockIdx.x * blockDim.x + threadIdx.x;
    int elem = t & (NELEM - 1);
    int cq   = t >> 16;
    float s = 0.f;
#pragma unroll 4
    for (int c = cq * (NIB/4); c < (cq + 1) * (NIB/4); ++c)
        s += g_S1part[(size_t)c * NELEM + elem];
    g_red1[t] = s;
}

// ---------------------------------------------------------------------------
// K4b: sum 4 stage-A partials + squash -> output.
// ---------------------------------------------------------------------------
__global__ void caps_squash_out(float* __restrict__ out)
{
    int t = blockIdx.x * blockDim.x + threadIdx.x;
    float s = g_red1[t] + g_red1[NELEM + t] + g_red1[2*NELEM + t] + g_red1[3*NELEM + t];
    float n2 = s * s;
#pragma unroll
    for (int off = 1; off < 16; off <<= 1)
        n2 += __shfl_xor_sync(0xffffffffu, n2, off);
    float f = sqrtf(n2) / (1.0f + n2);
    out[t] = s * f;
}

// ---------------------------------------------------------------------------
extern "C" void kernel_launch(void* const* d_in, const int* in_sizes, int n_in,
                              void* d_out, int out_size)
{
    const float* X = (const float*)d_in[0];
    const float* W = (const float*)d_in[1];
    // defensive: identify by size (X = 4,194,304 ; W = 16,777,216)
    if (n_in >= 2 && in_sizes[0] == NI * NO * DO * DI && in_sizes[1] == NBATCH * NI * DI) {
        W = (const float*)d_in[0];
        X = (const float*)d_in[1];
    }

    dim3 grid1(4, NIB);        // K1-lite: 512 CTAs, 2/SM
    dim3 grid3(8, NIB);        // K3-fused: 1024 CTAs, 2/SM (bq fast -> W L2 reuse)
    caps_s0_mma<<<grid1, 256>>>(X, W);
    caps_red_s0<<<1024, 256>>>();
    caps_squash_v0<<<256, 256>>>();
    caps_route_fused<<<grid3, 256>>>(X, W);
    caps_red_s1<<<1024, 256>>>();
    caps_squash_out<<<256, 256>>>((float*)d_out);
}

// round 15
// speedup vs baseline: 1.3054x; 1.3054x over previous
#include <cuda_runtime.h>
#include <cuda_fp16.h>
#include <math.h>

// Problem dims (fixed by the dataset)
#define NBATCH 128
#define NI     2048
#define DI     16
#define NO     32
#define DO     16
#define JD     (NO * DO)          // 512

// K1 (mma) tiling: CTA = 128 b x 128 n (quarter of W) x II i's
#define II     16
#define NIB    (NI / II)          // 128 i-blocks
// K3 tiling: warp per (b, i-chunk)
#define WPB    32                 // warps (i-chunks) per batch
#define ICH3   (NI / WPB)         // 64 i per warp
#define NCH1   WPB                // 32 S1 partial chunks

#define NELEM  (NBATCH * JD)      // 65536

// Osm row stride in halves (128 data + 8 pad -> 272B rows, 4-bank shift/row)
#define OSTRIDE 136
// K1 dynamic smem: 2x Wbuf(2048h) + 2x Xbuf(2048h) + Osm(128*OSTRIDE h)
#define K1_SMEM_HALVES (4 * 2048 + 128 * OSTRIDE)
#define K1_SMEM_BYTES  (K1_SMEM_HALVES * 2)

// Deterministic buffers (no atomics anywhere).
// Xhat layout: [i][b][n] -- per-i tile contiguous (128 b x 512 n)
__device__ __half g_Xhat[(size_t)NI * NBATCH * JD];          // 268 MB fp16
__device__ float  g_S0part[(size_t)NIB * NBATCH * JD];       // 33.5 MB
__device__ float  g_S1part[(size_t)NCH1 * NBATCH * JD];      // 8.4 MB
__device__ float  g_red0[4 * NELEM];                         // 1 MB
__device__ float  g_red1[4 * NELEM];                         // 1 MB
__device__ float  g_V0[NBATCH * JD];

// ---------------------------------------------------------------------------
// mma.sync m16n8k16 f16 -> f32
// ---------------------------------------------------------------------------
__device__ __forceinline__ void mma16816(float& d0, float& d1, float& d2, float& d3,
                                         unsigned a0, unsigned a1, unsigned a2, unsigned a3,
                                         unsigned b0, unsigned b1)
{
    asm volatile(
        "mma.sync.aligned.m16n8k16.row.col.f32.f16.f16.f32 "
        "{%0,%1,%2,%3}, {%4,%5,%6,%7}, {%8,%9}, {%10,%11,%12,%13};"
        : "=f"(d0), "=f"(d1), "=f"(d2), "=f"(d3)
        : "r"(a0), "r"(a1), "r"(a2), "r"(a3), "r"(b0), "r"(b1),
          "f"(0.0f), "f"(0.0f), "f"(0.0f), "f"(0.0f));
}

__device__ __forceinline__ unsigned pkh2(float x, float y) {
    __half2 h = __floats2half2_rn(x, y);
    return *reinterpret_cast<unsigned*>(&h);
}

// ---------------------------------------------------------------------------
// K1 stage: LDG fp32 -> cvt fp16 -> STS into the given buffer (no reg holding)
// ---------------------------------------------------------------------------
__device__ __forceinline__ void k1_stage(unsigned* Wu, unsigned* Xu,
                                         const float* __restrict__ X,
                                         const float* __restrict__ W,
                                         int i, int nbase, int t)
{
#pragma unroll
    for (int r = 0; r < 2; ++r) {
        int e  = t + r * 256;
        int nl = e >> 2, k4 = e & 3;
        float4 v = *reinterpret_cast<const float4*>(
            W + ((size_t)i * JD + nbase + nl) * DI + k4 * 4);
        uint2 h; h.x = pkh2(v.x, v.y); h.y = pkh2(v.z, v.w);
        *reinterpret_cast<uint2*>(Wu + nl * 8 + k4 * 2) = h;
    }
#pragma unroll
    for (int r = 0; r < 2; ++r) {
        int e = t + r * 256;
        int b = e >> 2, k4 = e & 3;
        float4 v = *reinterpret_cast<const float4*>(
            X + ((size_t)b * NI + i) * DI + k4 * 4);
        uint2 h; h.x = pkh2(v.x, v.y); h.y = pkh2(v.z, v.w);
        *reinterpret_cast<uint2*>(Xu + b * 8 + k4 * 2) = h;
    }
}

// ---------------------------------------------------------------------------
// K1: X_hat (fp16, [i][b][n]) + S0 partials via tensor cores.
// grid (4 nq, NIB), block 256 (8 warps), 2 CTAs/SM.
// R15 change: DOUBLE-BUFFERED W/X staging (dynamic smem). Stage for i+1
// issues before i's compute; per-i syncs drop 3 -> 2.
// ---------------------------------------------------------------------------
__global__ __launch_bounds__(256, 2)
void caps_xhat_s0_mma(const float* __restrict__ X, const float* __restrict__ W)
{
    extern __shared__ __align__(16) __half smem_k1[];
    __half* Wsm = smem_k1;                    // [2][2048]
    __half* Xsm = smem_k1 + 2 * 2048;         // [2][2048]
    __half* Osm = smem_k1 + 4 * 2048;         // [128][OSTRIDE]

    const int nq    = blockIdx.x;
    const int iblk  = blockIdx.y;
    const int t     = threadIdx.x;
    const int w     = t >> 5;
    const int l     = t & 31;
    const int g     = l >> 2;       // fragment group (row)
    const int tq    = l & 3;        // fragment thread-in-group (col pair)
    const int nbase = nq * 128;

    float s0[16][4];                // [nt*8+mt][frag reg]
#pragma unroll
    for (int q = 0; q < 16; ++q) { s0[q][0]=0.f; s0[q][1]=0.f; s0[q][2]=0.f; s0[q][3]=0.f; }

    // prologue: stage buffer 0
    k1_stage(reinterpret_cast<unsigned*>(Wsm),
             reinterpret_cast<unsigned*>(Xsm), X, W, iblk * II, nbase, t);
    __syncthreads();

    for (int ii = 0; ii < II; ++ii) {
        const int i = iblk * II + ii;
        const int cur = ii & 1;

        // stage next i into the other buffer (LDG latency overlaps compute)
        if (ii + 1 < II) {
            const int nxt = cur ^ 1;
            k1_stage(reinterpret_cast<unsigned*>(Wsm + nxt * 2048),
                     reinterpret_cast<unsigned*>(Xsm + nxt * 2048),
                     X, W, i + 1, nbase, t);
        }

        unsigned* Wu = reinterpret_cast<unsigned*>(Wsm + cur * 2048);
        unsigned* Xu = reinterpret_cast<unsigned*>(Xsm + cur * 2048);

        // A fragments: 8 m-tiles
        unsigned a[8][4];
#pragma unroll
        for (int mt = 0; mt < 8; ++mt) {
            int base = (mt * 16 + g) * 8 + tq;
            a[mt][0] = Xu[base];
            a[mt][1] = Xu[base + 64];
            a[mt][2] = Xu[base + 4];
            a[mt][3] = Xu[base + 68];
        }
        // B fragments: this warp's 2 n-tiles
        unsigned bf[2][2];
#pragma unroll
        for (int nt = 0; nt < 2; ++nt) {
            int base = (w * 16 + nt * 8 + g) * 8 + tq;
            bf[nt][0] = Wu[base];
            bf[nt][1] = Wu[base + 4];
        }

#pragma unroll
        for (int nt = 0; nt < 2; ++nt) {
            const int nl = w * 16 + nt * 8 + tq * 2;   // n-local
#pragma unroll
            for (int mt = 0; mt < 8; ++mt) {
                float d0, d1, d2, d3;
                mma16816(d0, d1, d2, d3,
                         a[mt][0], a[mt][1], a[mt][2], a[mt][3],
                         bf[nt][0], bf[nt][1]);
                float* s = s0[nt * 8 + mt];
                s[0] += d0; s[1] += d1; s[2] += d2; s[3] += d3;
                const int bq = mt * 16 + g;
                // STS.32, conflict-free: bank = (4g + const + tq) mod 32
                *reinterpret_cast<unsigned*>(&Osm[bq * OSTRIDE + nl])
                    = pkh2(d0, d1);
                *reinterpret_cast<unsigned*>(&Osm[(bq + 8) * OSTRIDE + nl])
                    = pkh2(d2, d3);
            }
        }
        __syncthreads();   // frag LDS + Osm STS + next-stage STS complete

        // coalesced write-out: 2048 16B-chunks, 8 per thread.
        __half* xg = &g_Xhat[((size_t)i * NBATCH) * JD + nbase];
#pragma unroll
        for (int r = 0; r < 8; ++r) {
            int e  = t + r * 256;
            int b  = e >> 4, c16 = e & 15;
            uint4 v = *reinterpret_cast<const uint4*>(&Osm[b * OSTRIDE + c16 * 8]);
            *reinterpret_cast<uint4*>(&xg[(size_t)b * JD + c16 * 8]) = v;
        }
        __syncthreads();   // Osm reads done; staged buffer visible for next iter
    }

    // write S0 partials: [iblk][b][n] (amortized over II=16 i's)
    float* outp = g_S0part + (size_t)iblk * NELEM;
#pragma unroll
    for (int nt = 0; nt < 2; ++nt) {
        const int n = nbase + w * 16 + nt * 8 + tq * 2;
#pragma unroll
        for (int mt = 0; mt < 8; ++mt) {
            const float* s = s0[nt * 8 + mt];
            const int bq = mt * 16 + g;
            *reinterpret_cast<float2*>(&outp[(size_t)bq * JD + n])
                = make_float2(s[0], s[1]);
            *reinterpret_cast<float2*>(&outp[(size_t)(bq + 8) * JD + n])
                = make_float2(s[2], s[3]);
        }
    }
}

// ---------------------------------------------------------------------------
// K2a: stage-A reduce of S0 partials. 262144 threads, (elem, c-quarter).
// ---------------------------------------------------------------------------
__global__ void caps_red_s0()
{
    int t    = blockIdx.x * blockDim.x + threadIdx.x;
    int elem = t & (NELEM - 1);
    int cq   = t >> 16;
    float s = 0.f;
#pragma unroll 4
    for (int c = cq * (NIB/4); c < (cq + 1) * (NIB/4); ++c)
        s += g_S0part[(size_t)c * NELEM + elem];
    g_red0[t] = s;
}

// ---------------------------------------------------------------------------
// K2b: sum 4 stage-A partials + squash -> g_V0.
// ---------------------------------------------------------------------------
__global__ void caps_squash_v0()
{
    int t = blockIdx.x * blockDim.x + threadIdx.x;
    float s = g_red0[t] + g_red0[NELEM + t] + g_red0[2*NELEM + t] + g_red0[3*NELEM + t];
    s *= (1.0f / NO);
    float n2 = s * s;
#pragma unroll
    for (int off = 1; off < 16; off <<= 1)
        n2 += __shfl_xor_sync(0xffffffffu, n2, off);
    float f = sqrtf(n2) / (1.0f + n2);
    g_V0[t] = s * f;
}

// ---------------------------------------------------------------------------
// K3: warp per (b, i-chunk). lane = j. v0 and s1 in registers.
// Streams X_hat ([i][b][n]) once, one softmax per (b,i).
// No-max softmax (bounded logits) + split dot.  (R13-proven, unchanged.)
// ---------------------------------------------------------------------------
__global__ __launch_bounds__(256, 4)
void caps_route_s1()
{
    const int wid = blockIdx.x * 8 + (threadIdx.x >> 5);  // 0..4095
    const int j   = threadIdx.x & 31;
    const int b   = wid >> 5;          // 0..127
    const int ch  = wid & (WPB - 1);   // 0..31

    // v0[b][j][0..15] into registers
    float v[16];
    {
        const float4* vp = reinterpret_cast<const float4*>(
            &g_V0[((size_t)b * NO + j) * DO]);
#pragma unroll
        for (int q = 0; q < 4; ++q) {
            float4 x = vp[q];
            v[q*4+0] = x.x; v[q*4+1] = x.y; v[q*4+2] = x.z; v[q*4+3] = x.w;
        }
    }

    float s1[16];
#pragma unroll
    for (int d = 0; d < 16; ++d) s1[d] = 0.f;

    for (int iiv = 0; iiv < ICH3; iiv += 2) {
        const int i0 = ch * ICH3 + iiv;

        uint4 xr[2][2];
#pragma unroll
        for (int u = 0; u < 2; ++u) {
            const uint4* xp = reinterpret_cast<const uint4*>(
                &g_Xhat[((size_t)(i0 + u) * NBATCH + b) * JD + j * DO]);
            xr[u][0] = xp[0]; xr[u][1] = xp[1];
        }

#pragma unroll
        for (int u = 0; u < 2; ++u) {
            float xf[16];
            {
                const unsigned uu[8] = {xr[u][0].x, xr[u][0].y, xr[u][0].z, xr[u][0].w,
                                        xr[u][1].x, xr[u][1].y, xr[u][1].z, xr[u][1].w};
#pragma unroll
                for (int q = 0; q < 8; ++q) {
                    float2 f2 = __half22float2(*reinterpret_cast<const __half2*>(&uu[q]));
                    xf[q*2+0] = f2.x; xf[q*2+1] = f2.y;
                }
            }

            // b1 logit: two parallel 8-deep FMA chains
            float pa = 0.f, pb = 0.f;
#pragma unroll
            for (int d = 0; d < 8; ++d) {
                pa = fmaf(xf[2*d],     v[2*d],     pa);
                pb = fmaf(xf[2*d + 1], v[2*d + 1], pb);
            }
            float p = pa + pb;

            // softmax over the 32 lanes (j axis) -- no max pass (bounded logits)
            float e = __expf(p);
            float ss = e;
#pragma unroll
            for (int off = 16; off; off >>= 1)
                ss += __shfl_xor_sync(0xffffffffu, ss, off);
            float c = e / ss;

#pragma unroll
            for (int d = 0; d < 16; ++d) s1[d] = fmaf(c, xf[d], s1[d]);
        }
    }

    // store partials [ch][b][j][d]
    float* o = g_S1part + (((size_t)ch * NBATCH + b) * NO + j) * DO;
#pragma unroll
    for (int q = 0; q < 4; ++q)
        *reinterpret_cast<float4*>(o + q * 4)
            = make_float4(s1[q*4+0], s1[q*4+1], s1[q*4+2], s1[q*4+3]);
}

// ---------------------------------------------------------------------------
// K4a: stage-A reduce of S1 partials. 262144 threads, (elem, c-quarter).
// ---------------------------------------------------------------------------
__global__ void caps_red_s1()
{
    int t    = blockIdx.x * blockDim.x + threadIdx.x;
    int elem = t & (NELEM - 1);
    int cq   = t >> 16;
    float s = 0.f;
#pragma unroll
    for (int c = cq * (NCH1/4); c < (cq + 1) * (NCH1/4); ++c)
        s += g_S1part[(size_t)c * NELEM + elem];
    g_red1[t] = s;
}

// ---------------------------------------------------------------------------
// K4b: sum 4 stage-A partials + squash -> output.
// ---------------------------------------------------------------------------
__global__ void caps_squash_out(float* __restrict__ out)
{
    int t = blockIdx.x * blockDim.x + threadIdx.x;
    float s = g_red1[t] + g_red1[NELEM + t] + g_red1[2*NELEM + t] + g_red1[3*NELEM + t];
    float n2 = s * s;
#pragma unroll
    for (int off = 1; off < 16; off <<= 1)
        n2 += __shfl_xor_sync(0xffffffffu, n2, off);
    float f = sqrtf(n2) / (1.0f + n2);
    out[t] = s * f;
}

// ---------------------------------------------------------------------------
extern "C" void kernel_launch(void* const* d_in, const int* in_sizes, int n_in,
                              void* d_out, int out_size)
{
    const float* X = (const float*)d_in[0];
    const float* W = (const float*)d_in[1];
    // defensive: identify by size (X = 4,194,304 ; W = 16,777,216)
    if (n_in >= 2 && in_sizes[0] == NI * NO * DO * DI && in_sizes[1] == NBATCH * NI * DI) {
        W = (const float*)d_in[0];
        X = (const float*)d_in[1];
    }

    // opt-in dynamic smem for K1 (idempotent; host-side attribute, not a stream op)
    cudaFuncSetAttribute(caps_xhat_s0_mma,
                         cudaFuncAttributeMaxDynamicSharedMemorySize, K1_SMEM_BYTES);

    dim3 grid1(4, NIB);        // 512 CTAs, 2/SM
    caps_xhat_s0_mma<<<grid1, 256, K1_SMEM_BYTES>>>(X, W);
    caps_red_s0<<<1024, 256>>>();
    caps_squash_v0<<<256, 256>>>();
    caps_route_s1<<<512, 256>>>();
    caps_red_s1<<<1024, 256>>>();
    caps_squash_out<<<256, 256>>>((float*)d_out);
}

// round 16
// speedup vs baseline: 1.3473x; 1.0321x over previous
#include <cuda_runtime.h>
#include <cuda_fp16.h>
#include <math.h>

// Problem dims (fixed by the dataset)
#define NBATCH 128
#define NI     2048
#define DI     16
#define NO     32
#define DO     16
#define JD     (NO * DO)          // 512

// K1 (mma) tiling: CTA = 128 b x 128 n (quarter of W) x II i's
#define II     16
#define NIB    (NI / II)          // 128 i-blocks
// K3 tiling: warp per (b, i-chunk)
#define WPB    32                 // warps (i-chunks) per batch
#define ICH3   (NI / WPB)         // 64 i per warp
#define NCH1   WPB                // 32 S1 partial chunks

#define NELEM  (NBATCH * JD)      // 65536

// Osm row stride in halves (128 data + 8 pad -> 272B rows, 4-bank shift/row)
#define OSTRIDE 136

// Deterministic buffers (no atomics anywhere).
// Xhat layout: [i][b][n] -- per-i tile contiguous (128 b x 512 n)
__device__ __half g_Xhat[(size_t)NI * NBATCH * JD];          // 268 MB fp16
__device__ float  g_S0part[(size_t)NIB * NBATCH * JD];       // 33.5 MB
__device__ float  g_S1part[(size_t)NCH1 * NBATCH * JD];      // 8.4 MB
__device__ float  g_red0[4 * NELEM];                         // 1 MB
__device__ float  g_red1[4 * NELEM];                         // 1 MB
__device__ float  g_V0[NBATCH * JD];

// ---------------------------------------------------------------------------
// mma.sync m16n8k16 f16 -> f32
// ---------------------------------------------------------------------------
__device__ __forceinline__ void mma16816(float& d0, float& d1, float& d2, float& d3,
                                         unsigned a0, unsigned a1, unsigned a2, unsigned a3,
                                         unsigned b0, unsigned b1)
{
    asm volatile(
        "mma.sync.aligned.m16n8k16.row.col.f32.f16.f16.f32 "
        "{%0,%1,%2,%3}, {%4,%5,%6,%7}, {%8,%9}, {%10,%11,%12,%13};"
        : "=f"(d0), "=f"(d1), "=f"(d2), "=f"(d3)
        : "r"(a0), "r"(a1), "r"(a2), "r"(a3), "r"(b0), "r"(b1),
          "f"(0.0f), "f"(0.0f), "f"(0.0f), "f"(0.0f));
}

__device__ __forceinline__ unsigned pkh2(float x, float y) {
    __half2 h = __floats2half2_rn(x, y);
    return *reinterpret_cast<unsigned*>(&h);
}

// streaming (evict-first) 16B store / load for the X_hat stream
__device__ __forceinline__ void stg_cs_v4(void* p, uint4 v) {
    asm volatile("st.global.cs.v4.u32 [%0], {%1,%2,%3,%4};"
                 :: "l"(p), "r"(v.x), "r"(v.y), "r"(v.z), "r"(v.w) : "memory");
}
__device__ __forceinline__ uint4 ldg_cs_v4(const void* p) {
    uint4 v;
    asm volatile("ld.global.cs.v4.u32 {%0,%1,%2,%3}, [%4];"
                 : "=r"(v.x), "=r"(v.y), "=r"(v.z), "=r"(v.w) : "l"(p));
    return v;
}

// ---------------------------------------------------------------------------
// K1: X_hat (fp16, [i][b][n]) + S0 partials via tensor cores.
// grid (4 nq, NIB), block 256 (8 warps), 2 CTAs/SM.  (R13-proven structure;
// only change: X_hat write-out uses st.global.cs to keep L2 for S0part.)
// ---------------------------------------------------------------------------
__global__ __launch_bounds__(256, 2)
void caps_xhat_s0_mma(const float* __restrict__ X, const float* __restrict__ W)
{
    __shared__ __align__(16) __half Wsm[128 * 16];        // 4 KB  [nlocal][k]
    __shared__ __align__(16) __half Xsm[128 * 16];        // 4 KB  [b][k]
    __shared__ __align__(16) __half Osm[128 * OSTRIDE];   // 34 KB [b][n+pad]

    const int nq    = blockIdx.x;
    const int iblk  = blockIdx.y;
    const int t     = threadIdx.x;
    const int w     = t >> 5;
    const int l     = t & 31;
    const int g     = l >> 2;       // fragment group (row)
    const int tq    = l & 3;        // fragment thread-in-group (col pair)
    const int nbase = nq * 128;

    unsigned* Wu = reinterpret_cast<unsigned*>(Wsm);
    unsigned* Xu = reinterpret_cast<unsigned*>(Xsm);

    float s0[16][4];                // [nt*8+mt][frag reg]
#pragma unroll
    for (int q = 0; q < 16; ++q) { s0[q][0]=0.f; s0[q][1]=0.f; s0[q][2]=0.f; s0[q][3]=0.f; }

    for (int ii = 0; ii < II; ++ii) {
        const int i = iblk * II + ii;
        __syncthreads();   // Osm readout of prev iter done; Wsm/Xsm free
        // stage W quarter: 128n x 16k fp32 -> fp16 (512 float4, 2 per thread)
#pragma unroll
        for (int r = 0; r < 2; ++r) {
            int e  = t + r * 256;
            int nl = e >> 2, k4 = e & 3;
            float4 v = *reinterpret_cast<const float4*>(
                W + ((size_t)i * JD + nbase + nl) * DI + k4 * 4);
            uint2 h; h.x = pkh2(v.x, v.y); h.y = pkh2(v.z, v.w);
            *reinterpret_cast<uint2*>(Wu + nl * 8 + k4 * 2) = h;
        }
        // stage X: 128b x 16k fp32 -> fp16 (512 float4, 2 per thread)
#pragma unroll
        for (int r = 0; r < 2; ++r) {
            int e = t + r * 256;
            int b = e >> 2, k4 = e & 3;
            float4 v = *reinterpret_cast<const float4*>(
                X + ((size_t)b * NI + i) * DI + k4 * 4);
            uint2 h; h.x = pkh2(v.x, v.y); h.y = pkh2(v.z, v.w);
            *reinterpret_cast<uint2*>(Xu + b * 8 + k4 * 2) = h;
        }
        __syncthreads();

        // A fragments: 8 m-tiles
        unsigned a[8][4];
#pragma unroll
        for (int mt = 0; mt < 8; ++mt) {
            int base = (mt * 16 + g) * 8 + tq;
            a[mt][0] = Xu[base];
            a[mt][1] = Xu[base + 64];
            a[mt][2] = Xu[base + 4];
            a[mt][3] = Xu[base + 68];
        }
        // B fragments: this warp's 2 n-tiles
        unsigned bf[2][2];
#pragma unroll
        for (int nt = 0; nt < 2; ++nt) {
            int base = (w * 16 + nt * 8 + g) * 8 + tq;
            bf[nt][0] = Wu[base];
            bf[nt][1] = Wu[base + 4];
        }

#pragma unroll
        for (int nt = 0; nt < 2; ++nt) {
            const int nl = w * 16 + nt * 8 + tq * 2;   // n-local
#pragma unroll
            for (int mt = 0; mt < 8; ++mt) {
                float d0, d1, d2, d3;
                mma16816(d0, d1, d2, d3,
                         a[mt][0], a[mt][1], a[mt][2], a[mt][3],
                         bf[nt][0], bf[nt][1]);
                float* s = s0[nt * 8 + mt];
                s[0] += d0; s[1] += d1; s[2] += d2; s[3] += d3;
                const int bq = mt * 16 + g;
                // STS.32, conflict-free: bank = (4g + const + tq) mod 32
                *reinterpret_cast<unsigned*>(&Osm[bq * OSTRIDE + nl])
                    = pkh2(d0, d1);
                *reinterpret_cast<unsigned*>(&Osm[(bq + 8) * OSTRIDE + nl])
                    = pkh2(d2, d3);
            }
        }
        __syncthreads();

        // coalesced write-out: 2048 16B-chunks, 8 per thread, STREAMING (.cs)
        __half* xg = &g_Xhat[((size_t)i * NBATCH) * JD + nbase];
#pragma unroll
        for (int r = 0; r < 8; ++r) {
            int e  = t + r * 256;
            int b  = e >> 4, c16 = e & 15;
            uint4 v = *reinterpret_cast<const uint4*>(&Osm[b * OSTRIDE + c16 * 8]);
            stg_cs_v4(&xg[(size_t)b * JD + c16 * 8], v);
        }
    }

    // write S0 partials: [iblk][b][n] (default caching -- wants L2 residency)
    float* outp = g_S0part + (size_t)iblk * NELEM;
#pragma unroll
    for (int nt = 0; nt < 2; ++nt) {
        const int n = nbase + w * 16 + nt * 8 + tq * 2;
#pragma unroll
        for (int mt = 0; mt < 8; ++mt) {
            const float* s = s0[nt * 8 + mt];
            const int bq = mt * 16 + g;
            *reinterpret_cast<float2*>(&outp[(size_t)bq * JD + n])
                = make_float2(s[0], s[1]);
            *reinterpret_cast<float2*>(&outp[(size_t)(bq + 8) * JD + n])
                = make_float2(s[2], s[3]);
        }
    }
}

// ---------------------------------------------------------------------------
// K2a: stage-A reduce of S0 partials. 262144 threads, (elem, c-quarter).
// ---------------------------------------------------------------------------
__global__ void caps_red_s0()
{
    int t    = blockIdx.x * blockDim.x + threadIdx.x;
    int elem = t & (NELEM - 1);
    int cq   = t >> 16;
    float s = 0.f;
#pragma unroll 4
    for (int c = cq * (NIB/4); c < (cq + 1) * (NIB/4); ++c)
        s += g_S0part[(size_t)c * NELEM + elem];
    g_red0[t] = s;
}

// ---------------------------------------------------------------------------
// K2b: sum 4 stage-A partials + squash -> g_V0.
// ---------------------------------------------------------------------------
__global__ void caps_squash_v0()
{
    int t = blockIdx.x * blockDim.x + threadIdx.x;
    float s = g_red0[t] + g_red0[NELEM + t] + g_red0[2*NELEM + t] + g_red0[3*NELEM + t];
    s *= (1.0f / NO);
    float n2 = s * s;
#pragma unroll
    for (int off = 1; off < 16; off <<= 1)
        n2 += __shfl_xor_sync(0xffffffffu, n2, off);
    float f = sqrtf(n2) / (1.0f + n2);
    g_V0[t] = s * f;
}

// ---------------------------------------------------------------------------
// K3: warp per (b, i-chunk). lane = j. v0 and s1 in registers.
// Streams X_hat ([i][b][n]) once via ld.global.cs, one softmax per (b,i).
// No-max softmax (bounded logits) + split dot.  (R13-proven otherwise.)
// ---------------------------------------------------------------------------
__global__ __launch_bounds__(256, 4)
void caps_route_s1()
{
    const int wid = blockIdx.x * 8 + (threadIdx.x >> 5);  // 0..4095
    const int j   = threadIdx.x & 31;
    const int b   = wid >> 5;          // 0..127
    const int ch  = wid & (WPB - 1);   // 0..31

    // v0[b][j][0..15] into registers
    float v[16];
    {
        const float4* vp = reinterpret_cast<const float4*>(
            &g_V0[((size_t)b * NO + j) * DO]);
#pragma unroll
        for (int q = 0; q < 4; ++q) {
            float4 x = vp[q];
            v[q*4+0] = x.x; v[q*4+1] = x.y; v[q*4+2] = x.z; v[q*4+3] = x.w;
        }
    }

    float s1[16];
#pragma unroll
    for (int d = 0; d < 16; ++d) s1[d] = 0.f;

    for (int iiv = 0; iiv < ICH3; iiv += 2) {
        const int i0 = ch * ICH3 + iiv;

        uint4 xr[2][2];
#pragma unroll
        for (int u = 0; u < 2; ++u) {
            const __half* xp = &g_Xhat[((size_t)(i0 + u) * NBATCH + b) * JD + j * DO];
            xr[u][0] = ldg_cs_v4(xp);
            xr[u][1] = ldg_cs_v4(xp + 8);
        }

#pragma unroll
        for (int u = 0; u < 2; ++u) {
            float xf[16];
            {
                const unsigned uu[8] = {xr[u][0].x, xr[u][0].y, xr[u][0].z, xr[u][0].w,
                                        xr[u][1].x, xr[u][1].y, xr[u][1].z, xr[u][1].w};
#pragma unroll
                for (int q = 0; q < 8; ++q) {
                    float2 f2 = __half22float2(*reinterpret_cast<const __half2*>(&uu[q]));
                    xf[q*2+0] = f2.x; xf[q*2+1] = f2.y;
                }
            }

            // b1 logit: two parallel 8-deep FMA chains
            float pa = 0.f, pb = 0.f;
#pragma unroll
            for (int d = 0; d < 8; ++d) {
                pa = fmaf(xf[2*d],     v[2*d],     pa);
                pb = fmaf(xf[2*d + 1], v[2*d + 1], pb);
            }
            float p = pa + pb;

            // softmax over the 32 lanes (j axis) -- no max pass (bounded logits)
            float e = __expf(p);
            float ss = e;
#pragma unroll
            for (int off = 16; off; off >>= 1)
                ss += __shfl_xor_sync(0xffffffffu, ss, off);
            float c = e / ss;

#pragma unroll
            for (int d = 0; d < 16; ++d) s1[d] = fmaf(c, xf[d], s1[d]);
        }
    }

    // store partials [ch][b][j][d] (default caching -- wants L2 residency)
    float* o = g_S1part + (((size_t)ch * NBATCH + b) * NO + j) * DO;
#pragma unroll
    for (int q = 0; q < 4; ++q)
        *reinterpret_cast<float4*>(o + q * 4)
            = make_float4(s1[q*4+0], s1[q*4+1], s1[q*4+2], s1[q*4+3]);
}

// ---------------------------------------------------------------------------
// K4a: stage-A reduce of S1 partials. 262144 threads, (elem, c-quarter).
// ---------------------------------------------------------------------------
__global__ void caps_red_s1()
{
    int t    = blockIdx.x * blockDim.x + threadIdx.x;
    int elem = t & (NELEM - 1);
    int cq   = t >> 16;
    float s = 0.f;
#pragma unroll
    for (int c = cq * (NCH1/4); c < (cq + 1) * (NCH1/4); ++c)
        s += g_S1part[(size_t)c * NELEM + elem];
    g_red1[t] = s;
}

// ---------------------------------------------------------------------------
// K4b: sum 4 stage-A partials + squash -> output.
// ---------------------------------------------------------------------------
__global__ void caps_squash_out(float* __restrict__ out)
{
    int t = blockIdx.x * blockDim.x + threadIdx.x;
    float s = g_red1[t] + g_red1[NELEM + t] + g_red1[2*NELEM + t] + g_red1[3*NELEM + t];
    float n2 = s * s;
#pragma unroll
    for (int off = 1; off < 16; off <<= 1)
        n2 += __shfl_xor_sync(0xffffffffu, n2, off);
    float f = sqrtf(n2) / (1.0f + n2);
    out[t] = s * f;
}

// ---------------------------------------------------------------------------
extern "C" void kernel_launch(void* const* d_in, const int* in_sizes, int n_in,
                              void* d_out, int out_size)
{
    const float* X = (const float*)d_in[0];
    const float* W = (const float*)d_in[1];
    // defensive: identify by size (X = 4,194,304 ; W = 16,777,216)
    if (n_in >= 2 && in_sizes[0] == NI * NO * DO * DI && in_sizes[1] == NBATCH * NI * DI) {
        W = (const float*)d_in[0];
        X = (const float*)d_in[1];
    }

    dim3 grid1(4, NIB);        // 512 CTAs, 2/SM
    caps_xhat_s0_mma<<<grid1, 256>>>(X, W);
    caps_red_s0<<<1024, 256>>>();
    caps_squash_v0<<<256, 256>>>();
    caps_route_s1<<<512, 256>>>();
    caps_red_s1<<<1024, 256>>>();
    caps_squash_out<<<256, 256>>>((float*)d_out);
}